// round 2
// baseline (speedup 1.0000x reference)
#include <cuda_runtime.h>

// PZCell as a chunked parallel scan.
// y[t] = b0 x[t] + b1 x[t-1] + b2 x[t-2] - a1 y[t-1] - a2 y[t-2]   (den == 1)
// One warp per row; each lane owns a 64-step chunk:
//   Phase A: FIR + zero-state recurrence (z kept in registers)
//   Phase B: affine Kogge-Stone scan of chunk end-states (T = M^64 constant)
//   Phase C: add homogeneous response from entry state, store.

namespace {
constexpr int T_LEN  = 2048;
constexpr int B_ROWS = 4096;
constexpr int L      = 64;    // chunk length (T_LEN / 32 lanes)
constexpr int RPB    = 8;     // rows (warps) per block
constexpr int THREADS = 32 * RPB;
}

__global__ void __launch_bounds__(THREADS, 2)
pz2_kernel(const float* __restrict__ x, const float* __restrict__ gain_ri,
           const float* __restrict__ poles_ri, const float* __restrict__ zeros_ri,
           float* __restrict__ out)
{
    const int  lane = threadIdx.x & 31;
    const int  row  = blockIdx.x * RPB + (threadIdx.x >> 5);
    const long base = (long)row * T_LEN + lane * L;
    const float* xr = x   + base;
    float*       yr = out + base;

    // ---- coefficients ----
    const float gr = gain_ri[0],  gi = gain_ri[1];
    const float pr0 = poles_ri[0], pi0 = poles_ri[1];
    const float pr1 = poles_ri[2], pi1 = poles_ri[3];
    const float zr0 = zeros_ri[0], zi0 = zeros_ri[1];
    const float zr1 = zeros_ri[2], zi1 = zeros_ri[3];
    const float a1 = -(pr0 + pr1);
    const float a2 = pr0 * pr1 - pi0 * pi1;
    const float zc1r = -(zr0 + zr1), zc1i = -(zi0 + zi1);
    const float zc2r = zr0 * zr1 - zi0 * zi1;
    const float zc2i = zr0 * zi1 + zi0 * zr1;
    const float b0 = gr;
    const float b1 = gr * zc1r - gi * zc1i;
    const float b2 = gr * zc2r - gi * zc2i;
    const float A2 = a1 * a1 - a2;   // 2-step jump coeffs
    const float Bc = a1 * a2;

    // ---- boundary x[-1], x[-2] from neighbor lane's last group ----
    float4 xlast = *reinterpret_cast<const float4*>(xr + L - 4);
    float x1 = __shfl_up_sync(0xffffffffu, xlast.w, 1);
    float x2 = __shfl_up_sync(0xffffffffu, xlast.z, 1);
    if (lane == 0) { x1 = 0.f; x2 = 0.f; }

    // ---- Phase A: FIR + zero-state recurrence, z in registers ----
    float z[L];
    float p = 0.f, q = 0.f;   // z[t-1], z[t-2]
    #pragma unroll
    for (int g = 0; g < L / 4; ++g) {
        float4 xv = (g == L / 4 - 1) ? xlast
                                     : *reinterpret_cast<const float4*>(xr + 4 * g);
        float u0 = fmaf(b0, xv.x, fmaf(b1, x1,   b2 * x2));
        float u1 = fmaf(b0, xv.y, fmaf(b1, xv.x, b2 * x1));
        float u2 = fmaf(b0, xv.z, fmaf(b1, xv.y, b2 * xv.x));
        float u3 = fmaf(b0, xv.w, fmaf(b1, xv.z, b2 * xv.y));
        x2 = xv.z; x1 = xv.w;
        float w1 = fmaf(-a1, u0, u1);
        float w3 = fmaf(-a1, u2, u3);
        float yA = fmaf(-a1, p,  fmaf(-a2, q,  u0));
        float yB = fmaf( A2, p,  fmaf( Bc, q,  w1));
        float yC = fmaf(-a1, yB, fmaf(-a2, yA, u2));
        float yD = fmaf( A2, yB, fmaf( Bc, yA, w3));
        p = yD; q = yC;
        z[4*g+0] = yA; z[4*g+1] = yB; z[4*g+2] = yC; z[4*g+3] = yD;
    }

    // ---- T = M^L by repeated squaring, M = [[-a1,-a2],[1,0]] ----
    float m00 = -a1, m01 = -a2, m10 = 1.f, m11 = 0.f;
    #pragma unroll
    for (int i = 0; i < 6; ++i) {   // M^2 .. M^64
        float t00 = m00*m00 + m01*m10;
        float t01 = m00*m01 + m01*m11;
        float t10 = m10*m00 + m11*m10;
        float t11 = m10*m01 + m11*m11;
        m00 = t00; m01 = t01; m10 = t10; m11 = t11;
    }

    // ---- Phase B: inclusive affine scan over lanes (chunks) ----
    // Element l: f_l(s) = T s + d_l, d_l = (z[63], z[62]) of lane l.
    float vx = p, vy = q;
    #pragma unroll
    for (int i = 0; i < 5; ++i) {
        float ox = __shfl_up_sync(0xffffffffu, vx, 1u << i);
        float oy = __shfl_up_sync(0xffffffffu, vy, 1u << i);
        if (lane >= (1 << i)) {
            vx = fmaf(m00, ox, fmaf(m01, oy, vx));
            vy = fmaf(m10, ox, fmaf(m11, oy, vy));
        }
        if (i < 4) {   // square the segment matrix for the next step
            float t00 = m00*m00 + m01*m10;
            float t01 = m00*m01 + m01*m11;
            float t10 = m10*m00 + m11*m10;
            float t11 = m10*m01 + m11*m11;
            m00 = t00; m01 = t01; m10 = t10; m11 = t11;
        }
    }
    // exclusive: entry state of this lane's chunk = previous lane's exit state
    float hp = __shfl_up_sync(0xffffffffu, vx, 1);  // y[-1]
    float hq = __shfl_up_sync(0xffffffffu, vy, 1);  // y[-2]
    if (lane == 0) { hp = 0.f; hq = 0.f; }

    // ---- Phase C: homogeneous response + store ----
    float h1 = hp, h2 = hq;
    #pragma unroll
    for (int g = 0; g < L / 4; ++g) {
        float hA = fmaf(-a1, h1, -a2 * h2);
        float hB = fmaf( A2, h1,  Bc * h2);
        float hC = fmaf(-a1, hB, -a2 * hA);
        float hD = fmaf( A2, hB,  Bc * hA);
        h2 = hC; h1 = hD;
        float4 yo = make_float4(z[4*g+0] + hA, z[4*g+1] + hB,
                                z[4*g+2] + hC, z[4*g+3] + hD);
        *reinterpret_cast<float4*>(yr + 4 * g) = yo;
    }
}

extern "C" void kernel_launch(void* const* d_in, const int* in_sizes, int n_in,
                              void* d_out, int out_size) {
    (void)in_sizes; (void)n_in; (void)out_size;
    const float* x        = (const float*)d_in[0];
    const float* gain_ri  = (const float*)d_in[1];
    const float* poles_ri = (const float*)d_in[2];
    const float* zeros_ri = (const float*)d_in[3];
    float* out = (float*)d_out;

    pz2_kernel<<<B_ROWS / RPB, THREADS>>>(x, gain_ri, poles_ri, zeros_ri, out);
}

// round 3
// speedup vs baseline: 1.5551x; 1.5551x over previous
#include <cuda_runtime.h>

// PZCell biquad via warp-per-row parallel scan, SMEM-staged for coalescing.
// y[t] = b0 x[t] + b1 x[t-1] + b2 x[t-2] - a1 y[t-1] - a2 y[t-2]   (den == 1)
// Each lane owns a 64-step chunk held in a padded SMEM tile:
//   load (coalesced) -> Phase A: zero-state recurrence in place ->
//   Phase B: affine Kogge-Stone lane scan (T = M^64) ->
//   Phase C: add homogeneous response in place -> store (coalesced).

namespace {
constexpr int T_LEN  = 2048;
constexpr int B_ROWS = 4096;
constexpr int L      = 64;                 // chunk per lane
constexpr int PITCH  = 68;                 // padded chunk pitch (floats), 17 x float4
constexpr int RPB    = 4;                  // rows (warps) per block
constexpr int THREADS = 32 * RPB;
constexpr int ROW_SMEM = 32 * PITCH;       // floats per row tile
constexpr int SMEM_BYTES = RPB * ROW_SMEM * (int)sizeof(float);  // 34816
}

__global__ void __launch_bounds__(THREADS, 6)
pz3_kernel(const float* __restrict__ x, const float* __restrict__ gain_ri,
           const float* __restrict__ poles_ri, const float* __restrict__ zeros_ri,
           float* __restrict__ out)
{
    extern __shared__ float sbuf[];
    const int  lane = threadIdx.x & 31;
    const int  w    = threadIdx.x >> 5;
    const int  row  = blockIdx.x * RPB + w;
    const float* xr = x   + (long)row * T_LEN;
    float*       yr = out + (long)row * T_LEN;
    float* sb  = sbuf + w * ROW_SMEM;          // this warp's private tile
    float* myc = sb + lane * PITCH;            // this lane's chunk

    // ---- coalesced load: gmem row -> padded smem tile ----
    #pragma unroll
    for (int k = 0; k < 16; ++k) {
        float4 v = *reinterpret_cast<const float4*>(xr + k * 128 + lane * 4);
        int chunk = 2 * k + (lane >> 4);
        int off   = (lane & 15) * 4;
        *reinterpret_cast<float4*>(sb + chunk * PITCH + off) = v;
    }
    __syncwarp();

    // ---- coefficients ----
    const float gr = gain_ri[0],  gi = gain_ri[1];
    const float pr0 = poles_ri[0], pi0 = poles_ri[1];
    const float pr1 = poles_ri[2], pi1 = poles_ri[3];
    const float zr0 = zeros_ri[0], zi0 = zeros_ri[1];
    const float zr1 = zeros_ri[2], zi1 = zeros_ri[3];
    const float a1 = -(pr0 + pr1);
    const float a2 = pr0 * pr1 - pi0 * pi1;
    const float zc1r = -(zr0 + zr1), zc1i = -(zi0 + zi1);
    const float zc2r = zr0 * zr1 - zi0 * zi1;
    const float zc2i = zr0 * zi1 + zi0 * zr1;
    const float b0 = gr;
    const float b1 = gr * zc1r - gi * zc1i;
    const float b2 = gr * zc2r - gi * zc2i;
    const float A2 = a1 * a1 - a2;   // 2-step jump coefficients
    const float Bc = a1 * a2;

    // ---- boundary x[-1], x[-2]: tail of previous lane's chunk ----
    float x1 = 0.f, x2 = 0.f;
    if (lane > 0) {
        x1 = sb[(lane - 1) * PITCH + 63];
        x2 = sb[(lane - 1) * PITCH + 62];
    }

    // ---- Phase A: zero-entry-state recurrence, z written in place ----
    float p = 0.f, q = 0.f;   // z[t-1], z[t-2]
    #pragma unroll
    for (int g = 0; g < L / 4; ++g) {
        float4 xv = *reinterpret_cast<float4*>(myc + 4 * g);
        float u0 = fmaf(b0, xv.x, fmaf(b1, x1,   b2 * x2));
        float u1 = fmaf(b0, xv.y, fmaf(b1, xv.x, b2 * x1));
        float u2 = fmaf(b0, xv.z, fmaf(b1, xv.y, b2 * xv.x));
        float u3 = fmaf(b0, xv.w, fmaf(b1, xv.z, b2 * xv.y));
        x2 = xv.z; x1 = xv.w;
        float w1 = fmaf(-a1, u0, u1);
        float w3 = fmaf(-a1, u2, u3);
        float yA = fmaf(-a1, p,  fmaf(-a2, q,  u0));
        float yB = fmaf( A2, p,  fmaf( Bc, q,  w1));
        float yC = fmaf(-a1, yB, fmaf(-a2, yA, u2));
        float yD = fmaf( A2, yB, fmaf( Bc, yA, w3));
        p = yD; q = yC;
        *reinterpret_cast<float4*>(myc + 4 * g) = make_float4(yA, yB, yC, yD);
    }

    // ---- T = M^64 via 6 squarings, M = [[-a1,-a2],[1,0]] ----
    float m00 = -a1, m01 = -a2, m10 = 1.f, m11 = 0.f;
    #pragma unroll
    for (int i = 0; i < 6; ++i) {
        float t00 = m00*m00 + m01*m10;
        float t01 = m00*m01 + m01*m11;
        float t10 = m10*m00 + m11*m10;
        float t11 = m10*m01 + m11*m11;
        m00 = t00; m01 = t01; m10 = t10; m11 = t11;
    }

    // ---- Phase B: inclusive affine scan over lanes ----
    float vx = p, vy = q;
    #pragma unroll
    for (int i = 0; i < 5; ++i) {
        float ox = __shfl_up_sync(0xffffffffu, vx, 1u << i);
        float oy = __shfl_up_sync(0xffffffffu, vy, 1u << i);
        if (lane >= (1 << i)) {
            vx = fmaf(m00, ox, fmaf(m01, oy, vx));
            vy = fmaf(m10, ox, fmaf(m11, oy, vy));
        }
        if (i < 4) {
            float t00 = m00*m00 + m01*m10;
            float t01 = m00*m01 + m01*m11;
            float t10 = m10*m00 + m11*m10;
            float t11 = m10*m01 + m11*m11;
            m00 = t00; m01 = t01; m10 = t10; m11 = t11;
        }
    }
    float hp = __shfl_up_sync(0xffffffffu, vx, 1);  // entry y[-1]
    float hq = __shfl_up_sync(0xffffffffu, vy, 1);  // entry y[-2]
    if (lane == 0) { hp = 0.f; hq = 0.f; }

    // ---- Phase C: add homogeneous response in place ----
    float h1 = hp, h2 = hq;
    #pragma unroll
    for (int g = 0; g < L / 4; ++g) {
        float hA = fmaf(-a1, h1, -a2 * h2);
        float hB = fmaf( A2, h1,  Bc * h2);
        float hC = fmaf(-a1, hB, -a2 * hA);
        float hD = fmaf( A2, hB,  Bc * hA);
        h2 = hC; h1 = hD;
        float4 zv = *reinterpret_cast<float4*>(myc + 4 * g);
        zv.x += hA; zv.y += hB; zv.z += hC; zv.w += hD;
        *reinterpret_cast<float4*>(myc + 4 * g) = zv;
    }
    __syncwarp();

    // ---- coalesced store: padded smem tile -> gmem row ----
    #pragma unroll
    for (int k = 0; k < 16; ++k) {
        int chunk = 2 * k + (lane >> 4);
        int off   = (lane & 15) * 4;
        float4 v = *reinterpret_cast<float4*>(sb + chunk * PITCH + off);
        *reinterpret_cast<float4*>(yr + k * 128 + lane * 4) = v;
    }
}

extern "C" void kernel_launch(void* const* d_in, const int* in_sizes, int n_in,
                              void* d_out, int out_size) {
    (void)in_sizes; (void)n_in; (void)out_size;
    const float* x        = (const float*)d_in[0];
    const float* gain_ri  = (const float*)d_in[1];
    const float* poles_ri = (const float*)d_in[2];
    const float* zeros_ri = (const float*)d_in[3];
    float* out = (float*)d_out;

    cudaFuncSetAttribute(pz3_kernel, cudaFuncAttributeMaxDynamicSharedMemorySize, SMEM_BYTES);
    pz3_kernel<<<B_ROWS / RPB, THREADS, SMEM_BYTES>>>(x, gain_ri, poles_ri, zeros_ri, out);
}